// round 1
// baseline (speedup 1.0000x reference)
#include <cuda_runtime.h>
#include <math.h>

#define DIMX 2048
#define KVDIM 512
#define HD 64
#define NH 32
#define BATCH 2
#define SEQ 2048
#define M_ROWS (BATCH*SEQ)
#define KSTRIDE 65

// ---- scratch (module-static device memory; no runtime allocation) ----
__device__ float g_tq[DIMX*DIMX];
__device__ float g_tk[KVDIM*DIMX];
__device__ float g_tv[KVDIM*DIMX];
__device__ float g_to[DIMX*DIMX];
__device__ float g_q [M_ROWS*DIMX];
__device__ float g_k [M_ROWS*KVDIM];
__device__ float g_v [M_ROWS*KVDIM];
__device__ float g_ao[M_ROWS*DIMX];
__device__ float g_partial[4][1024];
__device__ float g_thresh[4];

// ---- |w| mean (deterministic two-pass) ----
__global__ void abs_partial_kernel(const float* __restrict__ w, int n, int slot) {
    __shared__ float sd[256];
    float s = 0.f;
    for (int i = blockIdx.x*blockDim.x + threadIdx.x; i < n; i += gridDim.x*blockDim.x)
        s += fabsf(w[i]);
    sd[threadIdx.x] = s;
    __syncthreads();
    for (int st = 128; st; st >>= 1) {
        if (threadIdx.x < st) sd[threadIdx.x] += sd[threadIdx.x + st];
        __syncthreads();
    }
    if (threadIdx.x == 0) g_partial[slot][blockIdx.x] = sd[0];
}

__global__ void finalize_kernel() {
    int slot = blockIdx.x;
    __shared__ float sd[256];
    float s = 0.f;
    for (int i = threadIdx.x; i < 1024; i += 256) s += g_partial[slot][i];
    sd[threadIdx.x] = s;
    __syncthreads();
    for (int st = 128; st; st >>= 1) {
        if (threadIdx.x < st) sd[threadIdx.x] += sd[threadIdx.x + st];
        __syncthreads();
    }
    if (threadIdx.x == 0) {
        const int ncounts[4] = {DIMX*DIMX, KVDIM*DIMX, KVDIM*DIMX, DIMX*DIMX};
        float scale = sd[0] / (float)ncounts[slot];
        g_thresh[slot] = 0.05f * fmaxf(scale, 1e-6f);
    }
}

__global__ void ternarize_kernel(const float* __restrict__ w, float* __restrict__ t,
                                 int n, int slot) {
    int i = blockIdx.x*256 + threadIdx.x;
    if (i >= n) return;
    float th = g_thresh[slot];
    float v = w[i];
    t[i] = v > th ? 1.0f : (v < -th ? -1.0f : 0.0f);
}

// ---- C[M,N] = A[M,K] * B[N,K]^T   (both K-contiguous, row-major) ----
__global__ __launch_bounds__(256) void sgemm_tn(
    const float* __restrict__ A, const float* __restrict__ B,
    float* __restrict__ C, int M, int N, int K)
{
    __shared__ float As[8][128];
    __shared__ float Bs[8][128];
    int tid = threadIdx.x;
    const float* Ab = A + (size_t)blockIdx.y * 128 * K;
    const float* Bb = B + (size_t)blockIdx.x * 128 * K;
    int ty = tid >> 4, tx = tid & 15;

    float acc[8][8];
    #pragma unroll
    for (int i = 0; i < 8; i++)
        #pragma unroll
        for (int j = 0; j < 8; j++) acc[i][j] = 0.f;

    int lr = tid >> 1;          // 0..127
    int lc = (tid & 1) * 4;     // 0 or 4

    for (int k0 = 0; k0 < K; k0 += 8) {
        float4 av = *reinterpret_cast<const float4*>(Ab + (size_t)lr*K + k0 + lc);
        float4 bv = *reinterpret_cast<const float4*>(Bb + (size_t)lr*K + k0 + lc);
        As[lc+0][lr] = av.x; As[lc+1][lr] = av.y; As[lc+2][lr] = av.z; As[lc+3][lr] = av.w;
        Bs[lc+0][lr] = bv.x; Bs[lc+1][lr] = bv.y; Bs[lc+2][lr] = bv.z; Bs[lc+3][lr] = bv.w;
        __syncthreads();
        #pragma unroll
        for (int kk = 0; kk < 8; kk++) {
            float4 a0 = *reinterpret_cast<const float4*>(&As[kk][ty*8]);
            float4 a1 = *reinterpret_cast<const float4*>(&As[kk][ty*8+4]);
            float4 b0 = *reinterpret_cast<const float4*>(&Bs[kk][tx*8]);
            float4 b1 = *reinterpret_cast<const float4*>(&Bs[kk][tx*8+4]);
            float a[8] = {a0.x,a0.y,a0.z,a0.w,a1.x,a1.y,a1.z,a1.w};
            float b[8] = {b0.x,b0.y,b0.z,b0.w,b1.x,b1.y,b1.z,b1.w};
            #pragma unroll
            for (int i = 0; i < 8; i++)
                #pragma unroll
                for (int j = 0; j < 8; j++)
                    acc[i][j] = fmaf(a[i], b[j], acc[i][j]);
        }
        __syncthreads();
    }
    float* Cb = C + (size_t)(blockIdx.y*128 + ty*8) * N + blockIdx.x*128 + tx*8;
    #pragma unroll
    for (int i = 0; i < 8; i++) {
        *reinterpret_cast<float4*>(Cb + (size_t)i*N)     = make_float4(acc[i][0],acc[i][1],acc[i][2],acc[i][3]);
        *reinterpret_cast<float4*>(Cb + (size_t)i*N + 4) = make_float4(acc[i][4],acc[i][5],acc[i][6],acc[i][7]);
    }
}

// ---- causal GQA flash attention, fp32, 64x64 tiles ----
__global__ __launch_bounds__(256) void flash_kernel(
    const float* __restrict__ Q, const float* __restrict__ K,
    const float* __restrict__ V, float* __restrict__ O)
{
    extern __shared__ float smem[];
    float* Qs = smem;                    // 64*64
    float* Ks = Qs + 64*64;              // 64*KSTRIDE
    float* Vs = Ks + 64*KSTRIDE;         // 64*KSTRIDE
    float* Ps = Vs + 64*KSTRIDE;         // 64*64

    int qb = blockIdx.x, h = blockIdx.y, b = blockIdx.z;
    int g = h >> 2;   // KV_REPEAT = 4
    int tid = threadIdx.x;
    int ty = tid >> 4, tx = tid & 15;

    const float* Qg = Q + (size_t)(b*SEQ + qb*64) * DIMX + h*HD;
    #pragma unroll
    for (int t = 0; t < 16; t++) {
        int idx = tid + t*256;
        int r = idx >> 6, c = idx & 63;
        Qs[r*64 + c] = Qg[(size_t)r*DIMX + c];
    }

    float m_i[4], l_i[4], o_acc[4][4];
    #pragma unroll
    for (int i = 0; i < 4; i++) {
        m_i[i] = -INFINITY; l_i[i] = 0.f;
        #pragma unroll
        for (int j = 0; j < 4; j++) o_acc[i][j] = 0.f;
    }

    int nkb = qb + 1;
    for (int kb = 0; kb < nkb; kb++) {
        __syncthreads();   // previous PV done (and covers Q visibility on kb=0)
        const float* Kg = K + (size_t)(b*SEQ + kb*64) * KVDIM + g*HD;
        const float* Vg = V + (size_t)(b*SEQ + kb*64) * KVDIM + g*HD;
        #pragma unroll
        for (int t = 0; t < 16; t++) {
            int idx = tid + t*256;
            int r = idx >> 6, c = idx & 63;
            Ks[r*KSTRIDE + c] = Kg[(size_t)r*KVDIM + c];
            Vs[r*KSTRIDE + c] = Vg[(size_t)r*KVDIM + c];
        }
        __syncthreads();

        float s[4][4];
        #pragma unroll
        for (int i = 0; i < 4; i++)
            #pragma unroll
            for (int j = 0; j < 4; j++) s[i][j] = 0.f;

        for (int d = 0; d < 64; d++) {
            float qr[4], kr[4];
            #pragma unroll
            for (int i = 0; i < 4; i++) qr[i] = Qs[(ty*4+i)*64 + d];
            #pragma unroll
            for (int j = 0; j < 4; j++) kr[j] = Ks[(tx + 16*j)*KSTRIDE + d];
            #pragma unroll
            for (int i = 0; i < 4; i++)
                #pragma unroll
                for (int j = 0; j < 4; j++)
                    s[i][j] = fmaf(qr[i], kr[j], s[i][j]);
        }

        const float sm = 0.125f;   // 1/sqrt(64)
        if (kb == qb) {
            #pragma unroll
            for (int i = 0; i < 4; i++) {
                int qi = qb*64 + ty*4 + i;
                #pragma unroll
                for (int j = 0; j < 4; j++) {
                    int kj = kb*64 + tx + 16*j;
                    s[i][j] = (kj <= qi) ? s[i][j]*sm : -INFINITY;
                }
            }
        } else {
            #pragma unroll
            for (int i = 0; i < 4; i++)
                #pragma unroll
                for (int j = 0; j < 4; j++) s[i][j] *= sm;
        }

        #pragma unroll
        for (int i = 0; i < 4; i++) {
            float mx = s[i][0];
            #pragma unroll
            for (int j = 1; j < 4; j++) mx = fmaxf(mx, s[i][j]);
            #pragma unroll
            for (int off = 8; off; off >>= 1)
                mx = fmaxf(mx, __shfl_xor_sync(0xffffffffu, mx, off));
            float m_new = fmaxf(m_i[i], mx);
            float alpha = expf(m_i[i] - m_new);

            float rs = 0.f;
            #pragma unroll
            for (int j = 0; j < 4; j++) {
                float p = expf(s[i][j] - m_new);
                s[i][j] = p;
                rs += p;
            }
            #pragma unroll
            for (int off = 8; off; off >>= 1)
                rs += __shfl_xor_sync(0xffffffffu, rs, off);

            l_i[i] = l_i[i]*alpha + rs;
            m_i[i] = m_new;
            #pragma unroll
            for (int j = 0; j < 4; j++) {
                o_acc[i][j] *= alpha;
                Ps[(ty*4+i)*64 + tx + 16*j] = s[i][j];
            }
        }
        __syncthreads();

        for (int k = 0; k < 64; k++) {
            float pr[4], vr[4];
            #pragma unroll
            for (int i = 0; i < 4; i++) pr[i] = Ps[(ty*4+i)*64 + k];
            #pragma unroll
            for (int j = 0; j < 4; j++) vr[j] = Vs[k*KSTRIDE + tx + 16*j];
            #pragma unroll
            for (int i = 0; i < 4; i++)
                #pragma unroll
                for (int j = 0; j < 4; j++)
                    o_acc[i][j] = fmaf(pr[i], vr[j], o_acc[i][j]);
        }
    }

    float* Og = O + (size_t)(b*SEQ + qb*64) * DIMX + h*HD;
    #pragma unroll
    for (int i = 0; i < 4; i++) {
        float inv = 1.f / l_i[i];
        #pragma unroll
        for (int j = 0; j < 4; j++)
            Og[(size_t)(ty*4+i)*DIMX + tx + 16*j] = o_acc[i][j] * inv;
    }
}

extern "C" void kernel_launch(void* const* d_in, const int* in_sizes, int n_in,
                              void* d_out, int out_size)
{
    const float* x  = (const float*)d_in[0];
    const float* wq = (const float*)d_in[1];
    const float* wk = (const float*)d_in[2];
    const float* wv = (const float*)d_in[3];
    const float* wo = (const float*)d_in[4];
    float* out = (float*)d_out;

    float *tq, *tk, *tv, *to, *q, *k, *v, *ao;
    cudaGetSymbolAddress((void**)&tq, g_tq);
    cudaGetSymbolAddress((void**)&tk, g_tk);
    cudaGetSymbolAddress((void**)&tv, g_tv);
    cudaGetSymbolAddress((void**)&to, g_to);
    cudaGetSymbolAddress((void**)&q,  g_q);
    cudaGetSymbolAddress((void**)&k,  g_k);
    cudaGetSymbolAddress((void**)&v,  g_v);
    cudaGetSymbolAddress((void**)&ao, g_ao);

    // 1) thresholds
    abs_partial_kernel<<<1024, 256>>>(wq, DIMX*DIMX,  0);
    abs_partial_kernel<<<1024, 256>>>(wk, KVDIM*DIMX, 1);
    abs_partial_kernel<<<1024, 256>>>(wv, KVDIM*DIMX, 2);
    abs_partial_kernel<<<1024, 256>>>(wo, DIMX*DIMX,  3);
    finalize_kernel<<<4, 256>>>();

    // 2) ternarize
    ternarize_kernel<<<(DIMX*DIMX)/256,  256>>>(wq, tq, DIMX*DIMX,  0);
    ternarize_kernel<<<(KVDIM*DIMX)/256, 256>>>(wk, tk, KVDIM*DIMX, 1);
    ternarize_kernel<<<(KVDIM*DIMX)/256, 256>>>(wv, tv, KVDIM*DIMX, 2);
    ternarize_kernel<<<(DIMX*DIMX)/256,  256>>>(wo, to, DIMX*DIMX,  3);

    // 3) projections
    sgemm_tn<<<dim3(DIMX/128,  M_ROWS/128), 256>>>(x, tq, q, M_ROWS, DIMX,  DIMX);
    sgemm_tn<<<dim3(KVDIM/128, M_ROWS/128), 256>>>(x, tk, k, M_ROWS, KVDIM, DIMX);
    sgemm_tn<<<dim3(KVDIM/128, M_ROWS/128), 256>>>(x, tv, v, M_ROWS, KVDIM, DIMX);

    // 4) attention
    size_t smem = (size_t)(64*64 + 2*64*KSTRIDE + 64*64) * sizeof(float);
    cudaFuncSetAttribute(flash_kernel, cudaFuncAttributeMaxDynamicSharedMemorySize, (int)smem);
    flash_kernel<<<dim3(SEQ/64, NH, BATCH), 256, smem>>>(q, k, v, ao);

    // 5) output projection
    sgemm_tn<<<dim3(DIMX/128, M_ROWS/128), 256>>>(ao, to, out, M_ROWS, DIMX, DIMX);
}

// round 3
// speedup vs baseline: 2.6817x; 2.6817x over previous
#include <cuda_runtime.h>
#include <math.h>
#include <stdint.h>

#define DIMX 2048
#define KVDIM 512
#define QKV_N 3072
#define HD 64
#define NH 32
#define BATCH 2
#define SEQ 2048
#define M_ROWS (BATCH*SEQ)
#define QLD 68
#define VLD 72

// ---- scratch (module-static device memory; no runtime allocation) ----
__device__ float g_w  [QKV_N*DIMX];   // ternarized [wq;wk;wv], rows K-contiguous
__device__ float g_to [DIMX*DIMX];    // ternarized wo
__device__ float g_qkv[(size_t)M_ROWS*QKV_N];
__device__ float g_ao [(size_t)M_ROWS*DIMX];
__device__ float g_partial[4][1024];
__device__ float g_thresh[4];

__device__ __forceinline__ uint32_t f2tf(float f) {
    uint32_t u; asm("cvt.rna.tf32.f32 %0, %1;" : "=r"(u) : "f"(f)); return u;
}
__device__ __forceinline__ float f2tff(float f) { return __uint_as_float(f2tf(f)); }
__device__ __forceinline__ uint32_t fu(float f) { return __float_as_uint(f); }
__device__ __forceinline__ void split2(float v, float& hi, float& lo) {
    hi = f2tff(v);
    lo = f2tff(v - hi);
}

// ---- |w| mean (deterministic two-pass, float4) ----
__global__ void abs_partial_kernel(const float4* __restrict__ w, int n4, int slot) {
    __shared__ float sd[256];
    float s = 0.f;
    for (int i = blockIdx.x*blockDim.x + threadIdx.x; i < n4; i += gridDim.x*blockDim.x) {
        float4 v = w[i];
        s += fabsf(v.x) + fabsf(v.y) + fabsf(v.z) + fabsf(v.w);
    }
    sd[threadIdx.x] = s;
    __syncthreads();
    for (int st = 128; st; st >>= 1) {
        if (threadIdx.x < st) sd[threadIdx.x] += sd[threadIdx.x + st];
        __syncthreads();
    }
    if (threadIdx.x == 0) g_partial[slot][blockIdx.x] = sd[0];
}

__global__ void finalize_kernel() {
    int slot = blockIdx.x;
    __shared__ float sd[256];
    float s = 0.f;
    for (int i = threadIdx.x; i < 1024; i += 256) s += g_partial[slot][i];
    sd[threadIdx.x] = s;
    __syncthreads();
    for (int st = 128; st; st >>= 1) {
        if (threadIdx.x < st) sd[threadIdx.x] += sd[threadIdx.x + st];
        __syncthreads();
    }
    if (threadIdx.x == 0) {
        const int ncounts[4] = {DIMX*DIMX, KVDIM*DIMX, KVDIM*DIMX, DIMX*DIMX};
        float scale = sd[0] / (float)ncounts[slot];
        g_thresh[slot] = 0.05f * fmaxf(scale, 1e-6f);
    }
}

__global__ void ternarize_kernel(const float4* __restrict__ w, float4* __restrict__ t,
                                 int n4, int slot) {
    int i = blockIdx.x*256 + threadIdx.x;
    if (i >= n4) return;
    float th = g_thresh[slot];
    float4 v = w[i];
    float4 o;
    o.x = v.x > th ? 1.f : (v.x < -th ? -1.f : 0.f);
    o.y = v.y > th ? 1.f : (v.y < -th ? -1.f : 0.f);
    o.z = v.z > th ? 1.f : (v.z < -th ? -1.f : 0.f);
    o.w = v.w > th ? 1.f : (v.w < -th ? -1.f : 0.f);
    t[i] = o;
}

#define MMA_TF32(d, a, b0v, b1v)                                             \
    asm volatile("mma.sync.aligned.m16n8k8.row.col.f32.tf32.tf32.f32 "       \
        "{%0,%1,%2,%3}, {%4,%5,%6,%7}, {%8,%9}, {%0,%1,%2,%3};"              \
        : "+f"(d[0]), "+f"(d[1]), "+f"(d[2]), "+f"(d[3])                     \
        : "r"(a[0]), "r"(a[1]), "r"(a[2]), "r"(a[3]), "r"(b0v), "r"(b1v))

// ---- C[M,N] = A[M,K] * B[N,K]^T  (A split into tf32 hi+lo; B ternary = exact) ----
__global__ __launch_bounds__(256) void mma_gemm_tn(
    const float* __restrict__ A, const float* __restrict__ B,
    float* __restrict__ C, int M, int N, int K)
{
    extern __shared__ float sm[];
    float* Ah = sm;              // 128*36
    float* Al = Ah + 128*36;     // 128*36
    float* Bs = Al + 128*36;     // 128*36
    int tid = threadIdx.x;
    int wid = tid >> 5, lane = tid & 31;
    int g = lane >> 2, t = lane & 3;
    int wm = (wid & 1) * 64, wn = (wid >> 1) * 32;
    const float* Ab = A + (size_t)blockIdx.y * 128 * K;
    const float* Bb = B + (size_t)blockIdx.x * 128 * K;

    float acc[4][4][4];
    #pragma unroll
    for (int mt = 0; mt < 4; mt++)
        #pragma unroll
        for (int nt = 0; nt < 4; nt++)
            #pragma unroll
            for (int r = 0; r < 4; r++) acc[mt][nt][r] = 0.f;

    int lr = tid >> 3;          // 0..31
    int lc = (tid & 7) * 4;     // 0,4,..,28

    for (int k0 = 0; k0 < K; k0 += 32) {
        #pragma unroll
        for (int it = 0; it < 4; it++) {
            int row = lr + it*32;
            float4 av = *reinterpret_cast<const float4*>(Ab + (size_t)row*K + k0 + lc);
            float4 bv = *reinterpret_cast<const float4*>(Bb + (size_t)row*K + k0 + lc);
            float4 h, l;
            split2(av.x, h.x, l.x); split2(av.y, h.y, l.y);
            split2(av.z, h.z, l.z); split2(av.w, h.w, l.w);
            *reinterpret_cast<float4*>(Ah + row*36 + lc) = h;
            *reinterpret_cast<float4*>(Al + row*36 + lc) = l;
            *reinterpret_cast<float4*>(Bs + row*36 + lc) = bv;  // ternary: exact in tf32
        }
        __syncthreads();
        #pragma unroll
        for (int ks = 0; ks < 4; ks++) {
            int kk = ks*8;
            uint32_t ah[4][4], al[4][4], b[4][2];
            #pragma unroll
            for (int mt = 0; mt < 4; mt++) {
                const float* ph = Ah + (wm + mt*16 + g)*36 + kk + t;
                const float* pl = Al + (wm + mt*16 + g)*36 + kk + t;
                ah[mt][0] = fu(ph[0]);       al[mt][0] = fu(pl[0]);
                ah[mt][1] = fu(ph[8*36]);    al[mt][1] = fu(pl[8*36]);
                ah[mt][2] = fu(ph[4]);       al[mt][2] = fu(pl[4]);
                ah[mt][3] = fu(ph[8*36+4]);  al[mt][3] = fu(pl[8*36+4]);
            }
            #pragma unroll
            for (int nt = 0; nt < 4; nt++) {
                const float* bb = Bs + (wn + nt*8 + g)*36 + kk + t;
                b[nt][0] = fu(bb[0]);
                b[nt][1] = fu(bb[4]);
            }
            #pragma unroll
            for (int mt = 0; mt < 4; mt++)
                #pragma unroll
                for (int nt = 0; nt < 4; nt++) {
                    MMA_TF32(acc[mt][nt], ah[mt], b[nt][0], b[nt][1]);
                    MMA_TF32(acc[mt][nt], al[mt], b[nt][0], b[nt][1]);
                }
        }
        __syncthreads();
    }
    #pragma unroll
    for (int mt = 0; mt < 4; mt++) {
        int r0 = blockIdx.y*128 + wm + mt*16 + g;
        #pragma unroll
        for (int nt = 0; nt < 4; nt++) {
            int c = blockIdx.x*128 + wn + nt*8 + t*2;
            *reinterpret_cast<float2*>(C + (size_t)r0*N + c) =
                make_float2(acc[mt][nt][0], acc[mt][nt][1]);
            *reinterpret_cast<float2*>(C + (size_t)(r0+8)*N + c) =
                make_float2(acc[mt][nt][2], acc[mt][nt][3]);
        }
    }
}

// ---- causal GQA flash attention, split-tf32 mma, 64x64 tiles, 4 warps ----
__global__ __launch_bounds__(128) void flash_kernel(
    const float* __restrict__ QKV, float* __restrict__ O)
{
    extern __shared__ float smf[];
    float* Qh = smf;               // 64*QLD
    float* Ql = Qh + 64*QLD;
    float* Kh = Ql + 64*QLD;
    float* Kl = Kh + 64*QLD;
    float* Ph = Kl + 64*QLD;
    float* Pl = Ph + 64*QLD;
    float* Vh = Pl + 64*QLD;       // 64*VLD
    float* Vl = Vh + 64*VLD;

    int qb = blockIdx.x, h = blockIdx.y, b = blockIdx.z;
    int gkv = h >> 2;   // KV_REPEAT = 4
    int tid = threadIdx.x;
    int wid = tid >> 5, lane = tid & 31;
    int g = lane >> 2, t = lane & 3;
    int wrow = wid * 16;

    // load Q tile (split to tf32 hi/lo)
    const float* Qg = QKV + (size_t)(b*SEQ + qb*64)*QKV_N + h*HD;
    {
        int c4 = (tid & 15)*4, r0 = tid >> 4;
        #pragma unroll
        for (int i = 0; i < 8; i++) {
            int row = r0 + i*8;
            float4 v = *reinterpret_cast<const float4*>(Qg + (size_t)row*QKV_N + c4);
            float4 hh, ll;
            split2(v.x, hh.x, ll.x); split2(v.y, hh.y, ll.y);
            split2(v.z, hh.z, ll.z); split2(v.w, hh.w, ll.w);
            *reinterpret_cast<float4*>(Qh + row*QLD + c4) = hh;
            *reinterpret_cast<float4*>(Ql + row*QLD + c4) = ll;
        }
    }

    float m_i[2] = {-INFINITY, -INFINITY};
    float l_i[2] = {0.f, 0.f};
    float o_acc[8][4];
    #pragma unroll
    for (int dt = 0; dt < 8; dt++)
        #pragma unroll
        for (int r = 0; r < 4; r++) o_acc[dt][r] = 0.f;

    for (int kb = 0; kb <= qb; kb++) {
        __syncthreads();   // prev PV reads done; also covers Q-load visibility
        const float* Kg = QKV + (size_t)(b*SEQ + kb*64)*QKV_N + DIMX + gkv*HD;
        const float* Vg = Kg + KVDIM;
        {
            int c4 = (tid & 15)*4, r0 = tid >> 4;
            #pragma unroll
            for (int i = 0; i < 8; i++) {
                int row = r0 + i*8;
                float4 kv = *reinterpret_cast<const float4*>(Kg + (size_t)row*QKV_N + c4);
                float4 vv = *reinterpret_cast<const float4*>(Vg + (size_t)row*QKV_N + c4);
                float4 khh, kll, vhh, vll;
                split2(kv.x, khh.x, kll.x); split2(kv.y, khh.y, kll.y);
                split2(kv.z, khh.z, kll.z); split2(kv.w, khh.w, kll.w);
                split2(vv.x, vhh.x, vll.x); split2(vv.y, vhh.y, vll.y);
                split2(vv.z, vhh.z, vll.z); split2(vv.w, vhh.w, vll.w);
                *reinterpret_cast<float4*>(Kh + row*QLD + c4) = khh;
                *reinterpret_cast<float4*>(Kl + row*QLD + c4) = kll;
                *reinterpret_cast<float4*>(Vh + row*VLD + c4) = vhh;
                *reinterpret_cast<float4*>(Vl + row*VLD + c4) = vll;
            }
        }
        __syncthreads();

        // S = Q @ K^T  (3-term split: qh·kh + qh·kl + ql·kh)
        float s[8][4];
        #pragma unroll
        for (int nt = 0; nt < 8; nt++)
            #pragma unroll
            for (int r = 0; r < 4; r++) s[nt][r] = 0.f;

        #pragma unroll
        for (int ks = 0; ks < 8; ks++) {
            int kk = ks*8;
            uint32_t ah[4], al[4];
            const float* ph = Qh + (wrow + g)*QLD + kk + t;
            const float* pl = Ql + (wrow + g)*QLD + kk + t;
            ah[0] = fu(ph[0]);       al[0] = fu(pl[0]);
            ah[1] = fu(ph[8*QLD]);   al[1] = fu(pl[8*QLD]);
            ah[2] = fu(ph[4]);       al[2] = fu(pl[4]);
            ah[3] = fu(ph[8*QLD+4]); al[3] = fu(pl[8*QLD+4]);
            #pragma unroll
            for (int nt = 0; nt < 8; nt++) {
                const float* bh = Kh + (nt*8 + g)*QLD + kk + t;
                const float* bl = Kl + (nt*8 + g)*QLD + kk + t;
                uint32_t bh0 = fu(bh[0]), bh1 = fu(bh[4]);
                uint32_t bl0 = fu(bl[0]), bl1 = fu(bl[4]);
                MMA_TF32(s[nt], ah, bh0, bh1);
                MMA_TF32(s[nt], ah, bl0, bl1);
                MMA_TF32(s[nt], al, bh0, bh1);
            }
        }

        const float smul = 0.125f;   // 1/sqrt(64)
        if (kb == qb) {
            int qr = wrow + g;   // local row (block-diagonal => local compare valid)
            #pragma unroll
            for (int nt = 0; nt < 8; nt++) {
                int c0 = nt*8 + t*2;
                s[nt][0] = (c0     <= qr)     ? s[nt][0]*smul : -INFINITY;
                s[nt][1] = (c0 + 1 <= qr)     ? s[nt][1]*smul : -INFINITY;
                s[nt][2] = (c0     <= qr + 8) ? s[nt][2]*smul : -INFINITY;
                s[nt][3] = (c0 + 1 <= qr + 8) ? s[nt][3]*smul : -INFINITY;
            }
        } else {
            #pragma unroll
            for (int nt = 0; nt < 8; nt++)
                #pragma unroll
                for (int r = 0; r < 4; r++) s[nt][r] *= smul;
        }

        // online softmax (2 rows per thread: g and g+8)
        #pragma unroll
        for (int r = 0; r < 2; r++) {
            float mx = -INFINITY;
            #pragma unroll
            for (int nt = 0; nt < 8; nt++)
                mx = fmaxf(mx, fmaxf(s[nt][2*r], s[nt][2*r+1]));
            mx = fmaxf(mx, __shfl_xor_sync(0xffffffffu, mx, 1));
            mx = fmaxf(mx, __shfl_xor_sync(0xffffffffu, mx, 2));
            float m_new = fmaxf(m_i[r], mx);
            float alpha = __expf(m_i[r] - m_new);
            float rs = 0.f;
            #pragma unroll
            for (int nt = 0; nt < 8; nt++) {
                float p0 = __expf(s[nt][2*r]   - m_new);
                float p1 = __expf(s[nt][2*r+1] - m_new);
                s[nt][2*r] = p0; s[nt][2*r+1] = p1;
                rs += p0 + p1;
            }
            rs += __shfl_xor_sync(0xffffffffu, rs, 1);
            rs += __shfl_xor_sync(0xffffffffu, rs, 2);
            l_i[r] = l_i[r]*alpha + rs;
            m_i[r] = m_new;
            #pragma unroll
            for (int dt = 0; dt < 8; dt++) {
                o_acc[dt][2*r]   *= alpha;
                o_acc[dt][2*r+1] *= alpha;
            }
        }

        // write split P to smem — warp writes+reads only its own 16 rows
        #pragma unroll
        for (int nt = 0; nt < 8; nt++) {
            float h0, l0, h1, l1, h2, l2, h3, l3;
            split2(s[nt][0], h0, l0); split2(s[nt][1], h1, l1);
            split2(s[nt][2], h2, l2); split2(s[nt][3], h3, l3);
            *reinterpret_cast<float2*>(Ph + (wrow+g)*QLD + nt*8 + t*2)   = make_float2(h0, h1);
            *reinterpret_cast<float2*>(Pl + (wrow+g)*QLD + nt*8 + t*2)   = make_float2(l0, l1);
            *reinterpret_cast<float2*>(Ph + (wrow+g+8)*QLD + nt*8 + t*2) = make_float2(h2, h3);
            *reinterpret_cast<float2*>(Pl + (wrow+g+8)*QLD + nt*8 + t*2) = make_float2(l2, l3);
        }
        __syncwarp();

        // O += P @ V  (3-term split)
        #pragma unroll
        for (int ks = 0; ks < 8; ks++) {
            int kk = ks*8;
            uint32_t ah[4], al[4];
            const float* ph = Ph + (wrow + g)*QLD + kk + t;
            const float* pl = Pl + (wrow + g)*QLD + kk + t;
            ah[0] = fu(ph[0]);       al[0] = fu(pl[0]);
            ah[1] = fu(ph[8*QLD]);   al[1] = fu(pl[8*QLD]);
            ah[2] = fu(ph[4]);       al[2] = fu(pl[4]);
            ah[3] = fu(ph[8*QLD+4]); al[3] = fu(pl[8*QLD+4]);
            #pragma unroll
            for (int dt = 0; dt < 8; dt++) {
                const float* bh = Vh + (kk + t)*VLD + dt*8 + g;
                const float* bl = Vl + (kk + t)*VLD + dt*8 + g;
                uint32_t bh0 = fu(bh[0]), bh1 = fu(bh[4*VLD]);
                uint32_t bl0 = fu(bl[0]), bl1 = fu(bl[4*VLD]);
                MMA_TF32(o_acc[dt], ah, bh0, bh1);
                MMA_TF32(o_acc[dt], ah, bl0, bl1);
                MMA_TF32(o_acc[dt], al, bh0, bh1);
            }
        }
    }

    float inv0 = 1.f / l_i[0], inv1 = 1.f / l_i[1];
    float* Og = O + (size_t)(b*SEQ + qb*64 + wrow + g)*DIMX + h*HD;
    #pragma unroll
    for (int dt = 0; dt < 8; dt++) {
        *reinterpret_cast<float2*>(Og + dt*8 + t*2) =
            make_float2(o_acc[dt][0]*inv0, o_acc[dt][1]*inv0);
        *reinterpret_cast<float2*>(Og + (size_t)8*DIMX + dt*8 + t*2) =
            make_float2(o_acc[dt][2]*inv1, o_acc[dt][3]*inv1);
    }
}

extern "C" void kernel_launch(void* const* d_in, const int* in_sizes, int n_in,
                              void* d_out, int out_size)
{
    const float* x  = (const float*)d_in[0];
    const float* wq = (const float*)d_in[1];
    const float* wk = (const float*)d_in[2];
    const float* wv = (const float*)d_in[3];
    const float* wo = (const float*)d_in[4];
    float* out = (float*)d_out;

    float *w3, *to, *qkv, *ao;
    cudaGetSymbolAddress((void**)&w3,  g_w);
    cudaGetSymbolAddress((void**)&to,  g_to);
    cudaGetSymbolAddress((void**)&qkv, g_qkv);
    cudaGetSymbolAddress((void**)&ao,  g_ao);

    // 1) thresholds
    abs_partial_kernel<<<1024, 256>>>((const float4*)wq, DIMX*DIMX/4,  0);
    abs_partial_kernel<<<1024, 256>>>((const float4*)wk, KVDIM*DIMX/4, 1);
    abs_partial_kernel<<<1024, 256>>>((const float4*)wv, KVDIM*DIMX/4, 2);
    abs_partial_kernel<<<1024, 256>>>((const float4*)wo, DIMX*DIMX/4,  3);
    finalize_kernel<<<4, 256>>>();

    // 2) ternarize (wq/wk/wv concatenated into one [3072,2048] weight)
    ternarize_kernel<<<(DIMX*DIMX/4)/256,  256>>>((const float4*)wq, (float4*)w3, DIMX*DIMX/4, 0);
    ternarize_kernel<<<(KVDIM*DIMX/4)/256, 256>>>((const float4*)wk,
        (float4*)(w3 + (size_t)DIMX*DIMX), KVDIM*DIMX/4, 1);
    ternarize_kernel<<<(KVDIM*DIMX/4)/256, 256>>>((const float4*)wv,
        (float4*)(w3 + (size_t)DIMX*DIMX + (size_t)KVDIM*DIMX), KVDIM*DIMX/4, 2);
    ternarize_kernel<<<(DIMX*DIMX/4)/256,  256>>>((const float4*)wo, (float4*)to, DIMX*DIMX/4, 3);

    // 3) fused QKV projection: [4096,2048] @ [3072,2048]^T
    size_t gsm = (size_t)3*128*36*sizeof(float);
    cudaFuncSetAttribute(mma_gemm_tn, cudaFuncAttributeMaxDynamicSharedMemorySize, (int)gsm);
    mma_gemm_tn<<<dim3(QKV_N/128, M_ROWS/128), 256, gsm>>>(x, w3, qkv, M_ROWS, QKV_N, DIMX);

    // 4) attention
    size_t smem = (size_t)(64*QLD*6 + 64*VLD*2) * sizeof(float);
    cudaFuncSetAttribute(flash_kernel, cudaFuncAttributeMaxDynamicSharedMemorySize, (int)smem);
    flash_kernel<<<dim3(SEQ/64, NH, BATCH), 128, smem>>>(qkv, ao);

    // 5) output projection
    mma_gemm_tn<<<dim3(DIMX/128, M_ROWS/128), 256, gsm>>>(ao, to, out, M_ROWS, DIMX, DIMX);
}

// round 4
// speedup vs baseline: 2.6848x; 1.0012x over previous
#include <cuda_runtime.h>
#include <math.h>
#include <stdint.h>

#define DIMX 2048
#define KVDIM 512
#define QKV_N 3072
#define HD 64
#define NH 32
#define BATCH 2
#define SEQ 2048
#define M_ROWS (BATCH*SEQ)
#define QLD 68
#define VLD 72

// ---- scratch (module-static device memory; no runtime allocation) ----
__device__ float g_w  [QKV_N*DIMX];   // ternarized [wq;wk;wv], rows K-contiguous
__device__ float g_to [DIMX*DIMX];    // ternarized wo
__device__ float g_qkv[(size_t)M_ROWS*QKV_N];
__device__ float g_ao [(size_t)M_ROWS*DIMX];
__device__ float g_partial[4][1024];
__device__ float g_thresh[4];

__device__ __forceinline__ uint32_t f2tf(float f) {
    uint32_t u; asm("cvt.rna.tf32.f32 %0, %1;" : "=r"(u) : "f"(f)); return u;
}
__device__ __forceinline__ float f2tff(float f) { return __uint_as_float(f2tf(f)); }
__device__ __forceinline__ uint32_t fu(float f) { return __float_as_uint(f); }
__device__ __forceinline__ void split2(float v, float& hi, float& lo) {
    hi = f2tff(v);
    lo = f2tff(v - hi);
}

// ---- |w| mean (deterministic two-pass, float4) ----
__global__ void abs_partial_kernel(const float4* __restrict__ w, int n4, int slot) {
    __shared__ float sd[256];
    float s = 0.f;
    for (int i = blockIdx.x*blockDim.x + threadIdx.x; i < n4; i += gridDim.x*blockDim.x) {
        float4 v = w[i];
        s += fabsf(v.x) + fabsf(v.y) + fabsf(v.z) + fabsf(v.w);
    }
    sd[threadIdx.x] = s;
    __syncthreads();
    for (int st = 128; st; st >>= 1) {
        if (threadIdx.x < st) sd[threadIdx.x] += sd[threadIdx.x + st];
        __syncthreads();
    }
    if (threadIdx.x == 0) g_partial[slot][blockIdx.x] = sd[0];
}

__global__ void finalize_kernel() {
    int slot = blockIdx.x;
    __shared__ float sd[256];
    float s = 0.f;
    for (int i = threadIdx.x; i < 1024; i += 256) s += g_partial[slot][i];
    sd[threadIdx.x] = s;
    __syncthreads();
    for (int st = 128; st; st >>= 1) {
        if (threadIdx.x < st) sd[threadIdx.x] += sd[threadIdx.x + st];
        __syncthreads();
    }
    if (threadIdx.x == 0) {
        const int ncounts[4] = {DIMX*DIMX, KVDIM*DIMX, KVDIM*DIMX, DIMX*DIMX};
        float scale = sd[0] / (float)ncounts[slot];
        g_thresh[slot] = 0.05f * fmaxf(scale, 1e-6f);
    }
}

__global__ void ternarize_kernel(const float4* __restrict__ w, float4* __restrict__ t,
                                 int n4, int slot) {
    int i = blockIdx.x*256 + threadIdx.x;
    if (i >= n4) return;
    float th = g_thresh[slot];
    float4 v = w[i];
    float4 o;
    o.x = v.x > th ? 1.f : (v.x < -th ? -1.f : 0.f);
    o.y = v.y > th ? 1.f : (v.y < -th ? -1.f : 0.f);
    o.z = v.z > th ? 1.f : (v.z < -th ? -1.f : 0.f);
    o.w = v.w > th ? 1.f : (v.w < -th ? -1.f : 0.f);
    t[i] = o;
}

#define MMA_TF32(d, a, b0v, b1v)                                             \
    asm volatile("mma.sync.aligned.m16n8k8.row.col.f32.tf32.tf32.f32 "       \
        "{%0,%1,%2,%3}, {%4,%5,%6,%7}, {%8,%9}, {%0,%1,%2,%3};"              \
        : "+f"(d[0]), "+f"(d[1]), "+f"(d[2]), "+f"(d[3])                     \
        : "r"(a[0]), "r"(a[1]), "r"(a[2]), "r"(a[3]), "r"(b0v), "r"(b1v))

// ---- C[M,N] = A[M,K] * B[N,K]^T  (A split into tf32 hi+lo; B ternary = exact) ----
__global__ __launch_bounds__(256) void mma_gemm_tn(
    const float* __restrict__ A, const float* __restrict__ B,
    float* __restrict__ C, int M, int N, int K)
{
    extern __shared__ float sm[];
    float* Ah = sm;              // 128*36
    float* Al = Ah + 128*36;     // 128*36
    float* Bs = Al + 128*36;     // 128*36
    int tid = threadIdx.x;
    int wid = tid >> 5, lane = tid & 31;
    int g = lane >> 2, t = lane & 3;
    int wm = (wid & 1) * 64, wn = (wid >> 1) * 32;
    const float* Ab = A + (size_t)blockIdx.y * 128 * K;
    const float* Bb = B + (size_t)blockIdx.x * 128 * K;

    float acc[4][4][4];
    #pragma unroll
    for (int mt = 0; mt < 4; mt++)
        #pragma unroll
        for (int nt = 0; nt < 4; nt++)
            #pragma unroll
            for (int r = 0; r < 4; r++) acc[mt][nt][r] = 0.f;

    int lr = tid >> 3;          // 0..31
    int lc = (tid & 7) * 4;     // 0,4,..,28

    for (int k0 = 0; k0 < K; k0 += 32) {
        #pragma unroll
        for (int it = 0; it < 4; it++) {
            int row = lr + it*32;
            float4 av = *reinterpret_cast<const float4*>(Ab + (size_t)row*K + k0 + lc);
            float4 bv = *reinterpret_cast<const float4*>(Bb + (size_t)row*K + k0 + lc);
            float4 h, l;
            split2(av.x, h.x, l.x); split2(av.y, h.y, l.y);
            split2(av.z, h.z, l.z); split2(av.w, h.w, l.w);
            *reinterpret_cast<float4*>(Ah + row*36 + lc) = h;
            *reinterpret_cast<float4*>(Al + row*36 + lc) = l;
            *reinterpret_cast<float4*>(Bs + row*36 + lc) = bv;  // ternary: exact in tf32
        }
        __syncthreads();
        #pragma unroll
        for (int ks = 0; ks < 4; ks++) {
            int kk = ks*8;
            uint32_t ah[4][4], al[4][4], b[4][2];
            #pragma unroll
            for (int mt = 0; mt < 4; mt++) {
                const float* ph = Ah + (wm + mt*16 + g)*36 + kk + t;
                const float* pl = Al + (wm + mt*16 + g)*36 + kk + t;
                ah[mt][0] = fu(ph[0]);       al[mt][0] = fu(pl[0]);
                ah[mt][1] = fu(ph[8*36]);    al[mt][1] = fu(pl[8*36]);
                ah[mt][2] = fu(ph[4]);       al[mt][2] = fu(pl[4]);
                ah[mt][3] = fu(ph[8*36+4]);  al[mt][3] = fu(pl[8*36+4]);
            }
            #pragma unroll
            for (int nt = 0; nt < 4; nt++) {
                const float* bb = Bs + (wn + nt*8 + g)*36 + kk + t;
                b[nt][0] = fu(bb[0]);
                b[nt][1] = fu(bb[4]);
            }
            #pragma unroll
            for (int mt = 0; mt < 4; mt++)
                #pragma unroll
                for (int nt = 0; nt < 4; nt++) {
                    MMA_TF32(acc[mt][nt], ah[mt], b[nt][0], b[nt][1]);
                    MMA_TF32(acc[mt][nt], al[mt], b[nt][0], b[nt][1]);
                }
        }
        __syncthreads();
    }
    #pragma unroll
    for (int mt = 0; mt < 4; mt++) {
        int r0 = blockIdx.y*128 + wm + mt*16 + g;
        #pragma unroll
        for (int nt = 0; nt < 4; nt++) {
            int c = blockIdx.x*128 + wn + nt*8 + t*2;
            *reinterpret_cast<float2*>(C + (size_t)r0*N + c) =
                make_float2(acc[mt][nt][0], acc[mt][nt][1]);
            *reinterpret_cast<float2*>(C + (size_t)(r0+8)*N + c) =
                make_float2(acc[mt][nt][2], acc[mt][nt][3]);
        }
    }
}

// ---- causal GQA flash attention, split-tf32 mma, 64x64 tiles, 4 warps ----
__global__ __launch_bounds__(128) void flash_kernel(
    const float* __restrict__ QKV, float* __restrict__ O)
{
    extern __shared__ float smf[];
    float* Qh = smf;               // 64*QLD
    float* Ql = Qh + 64*QLD;
    float* Kh = Ql + 64*QLD;
    float* Kl = Kh + 64*QLD;
    float* Ph = Kl + 64*QLD;
    float* Pl = Ph + 64*QLD;
    float* Vh = Pl + 64*QLD;       // 64*VLD
    float* Vl = Vh + 64*VLD;

    int qb = blockIdx.x, h = blockIdx.y, b = blockIdx.z;
    int gkv = h >> 2;   // KV_REPEAT = 4
    int tid = threadIdx.x;
    int wid = tid >> 5, lane = tid & 31;
    int g = lane >> 2, t = lane & 3;
    int wrow = wid * 16;

    // load Q tile (split to tf32 hi/lo)
    const float* Qg = QKV + (size_t)(b*SEQ + qb*64)*QKV_N + h*HD;
    {
        int c4 = (tid & 15)*4, r0 = tid >> 4;
        #pragma unroll
        for (int i = 0; i < 8; i++) {
            int row = r0 + i*8;
            float4 v = *reinterpret_cast<const float4*>(Qg + (size_t)row*QKV_N + c4);
            float4 hh, ll;
            split2(v.x, hh.x, ll.x); split2(v.y, hh.y, ll.y);
            split2(v.z, hh.z, ll.z); split2(v.w, hh.w, ll.w);
            *reinterpret_cast<float4*>(Qh + row*QLD + c4) = hh;
            *reinterpret_cast<float4*>(Ql + row*QLD + c4) = ll;
        }
    }

    float m_i[2] = {-INFINITY, -INFINITY};
    float l_i[2] = {0.f, 0.f};
    float o_acc[8][4];
    #pragma unroll
    for (int dt = 0; dt < 8; dt++)
        #pragma unroll
        for (int r = 0; r < 4; r++) o_acc[dt][r] = 0.f;

    for (int kb = 0; kb <= qb; kb++) {
        __syncthreads();   // prev PV reads done; also covers Q-load visibility
        const float* Kg = QKV + (size_t)(b*SEQ + kb*64)*QKV_N + DIMX + gkv*HD;
        const float* Vg = Kg + KVDIM;
        {
            int c4 = (tid & 15)*4, r0 = tid >> 4;
            #pragma unroll
            for (int i = 0; i < 8; i++) {
                int row = r0 + i*8;
                float4 kv = *reinterpret_cast<const float4*>(Kg + (size_t)row*QKV_N + c4);
                float4 vv = *reinterpret_cast<const float4*>(Vg + (size_t)row*QKV_N + c4);
                float4 khh, kll, vhh, vll;
                split2(kv.x, khh.x, kll.x); split2(kv.y, khh.y, kll.y);
                split2(kv.z, khh.z, kll.z); split2(kv.w, khh.w, kll.w);
                split2(vv.x, vhh.x, vll.x); split2(vv.y, vhh.y, vll.y);
                split2(vv.z, vhh.z, vll.z); split2(vv.w, vhh.w, vll.w);
                *reinterpret_cast<float4*>(Kh + row*QLD + c4) = khh;
                *reinterpret_cast<float4*>(Kl + row*QLD + c4) = kll;
                *reinterpret_cast<float4*>(Vh + row*VLD + c4) = vhh;
                *reinterpret_cast<float4*>(Vl + row*VLD + c4) = vll;
            }
        }
        __syncthreads();

        // S = Q @ K^T  (3-term split: qh·kh + qh·kl + ql·kh)
        float s[8][4];
        #pragma unroll
        for (int nt = 0; nt < 8; nt++)
            #pragma unroll
            for (int r = 0; r < 4; r++) s[nt][r] = 0.f;

        #pragma unroll
        for (int ks = 0; ks < 8; ks++) {
            int kk = ks*8;
            uint32_t ah[4], al[4];
            const float* ph = Qh + (wrow + g)*QLD + kk + t;
            const float* pl = Ql + (wrow + g)*QLD + kk + t;
            ah[0] = fu(ph[0]);       al[0] = fu(pl[0]);
            ah[1] = fu(ph[8*QLD]);   al[1] = fu(pl[8*QLD]);
            ah[2] = fu(ph[4]);       al[2] = fu(pl[4]);
            ah[3] = fu(ph[8*QLD+4]); al[3] = fu(pl[8*QLD+4]);
            #pragma unroll
            for (int nt = 0; nt < 8; nt++) {
                const float* bh = Kh + (nt*8 + g)*QLD + kk + t;
                const float* bl = Kl + (nt*8 + g)*QLD + kk + t;
                uint32_t bh0 = fu(bh[0]), bh1 = fu(bh[4]);
                uint32_t bl0 = fu(bl[0]), bl1 = fu(bl[4]);
                MMA_TF32(s[nt], ah, bh0, bh1);
                MMA_TF32(s[nt], ah, bl0, bl1);
                MMA_TF32(s[nt], al, bh0, bh1);
            }
        }

        const float smul = 0.125f;   // 1/sqrt(64)
        if (kb == qb) {
            int qr = wrow + g;   // local row (block-diagonal => local compare valid)
            #pragma unroll
            for (int nt = 0; nt < 8; nt++) {
                int c0 = nt*8 + t*2;
                s[nt][0] = (c0     <= qr)     ? s[nt][0]*smul : -INFINITY;
                s[nt][1] = (c0 + 1 <= qr)     ? s[nt][1]*smul : -INFINITY;
                s[nt][2] = (c0     <= qr + 8) ? s[nt][2]*smul : -INFINITY;
                s[nt][3] = (c0 + 1 <= qr + 8) ? s[nt][3]*smul : -INFINITY;
            }
        } else {
            #pragma unroll
            for (int nt = 0; nt < 8; nt++)
                #pragma unroll
                for (int r = 0; r < 4; r++) s[nt][r] *= smul;
        }

        // online softmax (2 rows per thread: g and g+8)
        #pragma unroll
        for (int r = 0; r < 2; r++) {
            float mx = -INFINITY;
            #pragma unroll
            for (int nt = 0; nt < 8; nt++)
                mx = fmaxf(mx, fmaxf(s[nt][2*r], s[nt][2*r+1]));
            mx = fmaxf(mx, __shfl_xor_sync(0xffffffffu, mx, 1));
            mx = fmaxf(mx, __shfl_xor_sync(0xffffffffu, mx, 2));
            float m_new = fmaxf(m_i[r], mx);
            float alpha = __expf(m_i[r] - m_new);
            float rs = 0.f;
            #pragma unroll
            for (int nt = 0; nt < 8; nt++) {
                float p0 = __expf(s[nt][2*r]   - m_new);
                float p1 = __expf(s[nt][2*r+1] - m_new);
                s[nt][2*r] = p0; s[nt][2*r+1] = p1;
                rs += p0 + p1;
            }
            rs += __shfl_xor_sync(0xffffffffu, rs, 1);
            rs += __shfl_xor_sync(0xffffffffu, rs, 2);
            l_i[r] = l_i[r]*alpha + rs;
            m_i[r] = m_new;
            #pragma unroll
            for (int dt = 0; dt < 8; dt++) {
                o_acc[dt][2*r]   *= alpha;
                o_acc[dt][2*r+1] *= alpha;
            }
        }

        // write split P to smem — warp writes+reads only its own 16 rows
        #pragma unroll
        for (int nt = 0; nt < 8; nt++) {
            float h0, l0, h1, l1, h2, l2, h3, l3;
            split2(s[nt][0], h0, l0); split2(s[nt][1], h1, l1);
            split2(s[nt][2], h2, l2); split2(s[nt][3], h3, l3);
            *reinterpret_cast<float2*>(Ph + (wrow+g)*QLD + nt*8 + t*2)   = make_float2(h0, h1);
            *reinterpret_cast<float2*>(Pl + (wrow+g)*QLD + nt*8 + t*2)   = make_float2(l0, l1);
            *reinterpret_cast<float2*>(Ph + (wrow+g+8)*QLD + nt*8 + t*2) = make_float2(h2, h3);
            *reinterpret_cast<float2*>(Pl + (wrow+g+8)*QLD + nt*8 + t*2) = make_float2(l2, l3);
        }
        __syncwarp();

        // O += P @ V  (3-term split)
        #pragma unroll
        for (int ks = 0; ks < 8; ks++) {
            int kk = ks*8;
            uint32_t ah[4], al[4];
            const float* ph = Ph + (wrow + g)*QLD + kk + t;
            const float* pl = Pl + (wrow + g)*QLD + kk + t;
            ah[0] = fu(ph[0]);       al[0] = fu(pl[0]);
            ah[1] = fu(ph[8*QLD]);   al[1] = fu(pl[8*QLD]);
            ah[2] = fu(ph[4]);       al[2] = fu(pl[4]);
            ah[3] = fu(ph[8*QLD+4]); al[3] = fu(pl[8*QLD+4]);
            #pragma unroll
            for (int dt = 0; dt < 8; dt++) {
                const float* bh = Vh + (kk + t)*VLD + dt*8 + g;
                const float* bl = Vl + (kk + t)*VLD + dt*8 + g;
                uint32_t bh0 = fu(bh[0]), bh1 = fu(bh[4*VLD]);
                uint32_t bl0 = fu(bl[0]), bl1 = fu(bl[4*VLD]);
                MMA_TF32(o_acc[dt], ah, bh0, bh1);
                MMA_TF32(o_acc[dt], ah, bl0, bl1);
                MMA_TF32(o_acc[dt], al, bh0, bh1);
            }
        }
    }

    float inv0 = 1.f / l_i[0], inv1 = 1.f / l_i[1];
    float* Og = O + (size_t)(b*SEQ + qb*64 + wrow + g)*DIMX + h*HD;
    #pragma unroll
    for (int dt = 0; dt < 8; dt++) {
        *reinterpret_cast<float2*>(Og + dt*8 + t*2) =
            make_float2(o_acc[dt][0]*inv0, o_acc[dt][1]*inv0);
        *reinterpret_cast<float2*>(Og + (size_t)8*DIMX + dt*8 + t*2) =
            make_float2(o_acc[dt][2]*inv1, o_acc[dt][3]*inv1);
    }
}

extern "C" void kernel_launch(void* const* d_in, const int* in_sizes, int n_in,
                              void* d_out, int out_size)
{
    const float* x  = (const float*)d_in[0];
    const float* wq = (const float*)d_in[1];
    const float* wk = (const float*)d_in[2];
    const float* wv = (const float*)d_in[3];
    const float* wo = (const float*)d_in[4];
    float* out = (float*)d_out;

    float *w3, *to, *qkv, *ao;
    cudaGetSymbolAddress((void**)&w3,  g_w);
    cudaGetSymbolAddress((void**)&to,  g_to);
    cudaGetSymbolAddress((void**)&qkv, g_qkv);
    cudaGetSymbolAddress((void**)&ao,  g_ao);

    // 1) thresholds
    abs_partial_kernel<<<1024, 256>>>((const float4*)wq, DIMX*DIMX/4,  0);
    abs_partial_kernel<<<1024, 256>>>((const float4*)wk, KVDIM*DIMX/4, 1);
    abs_partial_kernel<<<1024, 256>>>((const float4*)wv, KVDIM*DIMX/4, 2);
    abs_partial_kernel<<<1024, 256>>>((const float4*)wo, DIMX*DIMX/4,  3);
    finalize_kernel<<<4, 256>>>();

    // 2) ternarize (wq/wk/wv concatenated into one [3072,2048] weight)
    ternarize_kernel<<<(DIMX*DIMX/4)/256,  256>>>((const float4*)wq, (float4*)w3, DIMX*DIMX/4, 0);
    ternarize_kernel<<<(KVDIM*DIMX/4)/256, 256>>>((const float4*)wk,
        (float4*)(w3 + (size_t)DIMX*DIMX), KVDIM*DIMX/4, 1);
    ternarize_kernel<<<(KVDIM*DIMX/4)/256, 256>>>((const float4*)wv,
        (float4*)(w3 + (size_t)DIMX*DIMX + (size_t)KVDIM*DIMX), KVDIM*DIMX/4, 2);
    ternarize_kernel<<<(DIMX*DIMX/4)/256,  256>>>((const float4*)wo, (float4*)to, DIMX*DIMX/4, 3);

    // 3) fused QKV projection: [4096,2048] @ [3072,2048]^T
    size_t gsm = (size_t)3*128*36*sizeof(float);
    cudaFuncSetAttribute(mma_gemm_tn, cudaFuncAttributeMaxDynamicSharedMemorySize, (int)gsm);
    mma_gemm_tn<<<dim3(QKV_N/128, M_ROWS/128), 256, gsm>>>(x, w3, qkv, M_ROWS, QKV_N, DIMX);

    // 4) attention
    size_t smem = (size_t)(64*QLD*6 + 64*VLD*2) * sizeof(float);
    cudaFuncSetAttribute(flash_kernel, cudaFuncAttributeMaxDynamicSharedMemorySize, (int)smem);
    flash_kernel<<<dim3(SEQ/64, NH, BATCH), 128, smem>>>(qkv, ao);

    // 5) output projection
    mma_gemm_tn<<<dim3(DIMX/128, M_ROWS/128), 256, gsm>>>(ao, to, out, M_ROWS, DIMX, DIMX);
}

// round 6
// speedup vs baseline: 3.8457x; 1.4324x over previous
#include <cuda_runtime.h>
#include <math.h>
#include <stdint.h>

#define DIMX 2048
#define KVDIM 512
#define QKV_N 3072
#define HD 64
#define NH 32
#define BATCH 2
#define SEQ 2048
#define M_ROWS (BATCH*SEQ)
#define QPAD 68     // float2 stride for Q/K interleaved hi/lo smem
#define VPAD 72     // float stride for V smem

// ---- scratch (module-static device memory) ----
__device__ float g_w  [QKV_N*DIMX];
__device__ float g_to [DIMX*DIMX];
__device__ float g_qh [(size_t)M_ROWS*QKV_N];
__device__ float g_ql [(size_t)M_ROWS*QKV_N];
__device__ float g_ao [(size_t)M_ROWS*DIMX];
__device__ float g_partial[4][1024];
__device__ float g_thresh[4];

__device__ __forceinline__ uint32_t f2tf(float f) {
    uint32_t u; asm("cvt.rna.tf32.f32 %0, %1;" : "=r"(u) : "f"(f)); return u;
}
__device__ __forceinline__ float f2tff(float f) { return __uint_as_float(f2tf(f)); }
__device__ __forceinline__ uint32_t fu(float f) { return __float_as_uint(f); }
__device__ __forceinline__ void split2(float v, float& hi, float& lo) {
    hi = f2tff(v);
    lo = f2tff(v - hi);
}

// ---- |w| mean (deterministic two-pass, float4) ----
__global__ void abs_partial_kernel(const float4* __restrict__ w, int n4, int slot) {
    __shared__ float sd[256];
    float s0 = 0.f, s1 = 0.f;
    int stride = gridDim.x * blockDim.x;
    for (int i = blockIdx.x*blockDim.x + threadIdx.x; i < n4; i += 2*stride) {
        float4 v = w[i];
        s0 += fabsf(v.x) + fabsf(v.y) + fabsf(v.z) + fabsf(v.w);
        int j = i + stride;
        if (j < n4) {
            float4 u = w[j];
            s1 += fabsf(u.x) + fabsf(u.y) + fabsf(u.z) + fabsf(u.w);
        }
    }
    sd[threadIdx.x] = s0 + s1;
    __syncthreads();
    for (int st = 128; st; st >>= 1) {
        if (threadIdx.x < st) sd[threadIdx.x] += sd[threadIdx.x + st];
        __syncthreads();
    }
    if (threadIdx.x == 0) g_partial[slot][blockIdx.x] = sd[0];
}

__global__ void finalize_kernel() {
    int slot = blockIdx.x;
    __shared__ float sd[256];
    float s = 0.f;
    for (int i = threadIdx.x; i < 1024; i += 256) s += g_partial[slot][i];
    sd[threadIdx.x] = s;
    __syncthreads();
    for (int st = 128; st; st >>= 1) {
        if (threadIdx.x < st) sd[threadIdx.x] += sd[threadIdx.x + st];
        __syncthreads();
    }
    if (threadIdx.x == 0) {
        const int ncounts[4] = {DIMX*DIMX, KVDIM*DIMX, KVDIM*DIMX, DIMX*DIMX};
        float scale = sd[0] / (float)ncounts[slot];
        g_thresh[slot] = 0.05f * fmaxf(scale, 1e-6f);
    }
}

__global__ void ternarize_kernel(const float4* __restrict__ w, float4* __restrict__ t,
                                 int n4, int slot) {
    int i = blockIdx.x*256 + threadIdx.x;
    if (i >= n4) return;
    float th = g_thresh[slot];
    float4 v = w[i];
    float4 o;
    o.x = v.x > th ? 1.f : (v.x < -th ? -1.f : 0.f);
    o.y = v.y > th ? 1.f : (v.y < -th ? -1.f : 0.f);
    o.z = v.z > th ? 1.f : (v.z < -th ? -1.f : 0.f);
    o.w = v.w > th ? 1.f : (v.w < -th ? -1.f : 0.f);
    t[i] = o;
}

#define MMA_TF32(d, a, b0v, b1v)                                             \
    asm volatile("mma.sync.aligned.m16n8k8.row.col.f32.tf32.tf32.f32 "       \
        "{%0,%1,%2,%3}, {%4,%5,%6,%7}, {%8,%9}, {%0,%1,%2,%3};"              \
        : "+f"(d[0]), "+f"(d[1]), "+f"(d[2]), "+f"(d[3])                     \
        : "r"(a[0]), "r"(a[1]), "r"(a[2]), "r"(a[3]), "r"(b0v), "r"(b1v))

// ---- C[M,N] = A[M,K] * B[N,K]^T via tf32 mma; optional A split, optional split output ----
template<bool ASPLIT, bool SPLIT_OUT>
__global__ __launch_bounds__(256) void mma_gemm(
    const float* __restrict__ A, const float* __restrict__ B,
    float* __restrict__ C, float* __restrict__ Clo, int N, int K)
{
    extern __shared__ float sm[];
    float* Ah = sm;
    float* Al = ASPLIT ? (sm + 128*36) : sm;
    float* Bs = sm + (ASPLIT ? 2 : 1)*128*36;
    int tid = threadIdx.x;
    int wid = tid >> 5, lane = tid & 31;
    int g = lane >> 2, t = lane & 3;
    int wm = (wid & 1) * 64, wn = (wid >> 1) * 32;
    const float* Ab = A + (size_t)blockIdx.y * 128 * K;
    const float* Bb = B + (size_t)blockIdx.x * 128 * K;

    float acc[4][4][4];
    #pragma unroll
    for (int mt = 0; mt < 4; mt++)
        #pragma unroll
        for (int nt = 0; nt < 4; nt++)
            #pragma unroll
            for (int r = 0; r < 4; r++) acc[mt][nt][r] = 0.f;

    int lr = tid >> 1;
    int lc = (tid & 1) * 16;

    for (int k0 = 0; k0 < K; k0 += 32) {
        #pragma unroll
        for (int i = 0; i < 4; i++) {
            float4 av = *reinterpret_cast<const float4*>(Ab + (size_t)lr*K + k0 + lc + 4*i);
            float4 bv = *reinterpret_cast<const float4*>(Bb + (size_t)lr*K + k0 + lc + 4*i);
            if (ASPLIT) {
                float4 h, l;
                split2(av.x, h.x, l.x); split2(av.y, h.y, l.y);
                split2(av.z, h.z, l.z); split2(av.w, h.w, l.w);
                *reinterpret_cast<float4*>(Ah + lr*36 + lc + 4*i) = h;
                *reinterpret_cast<float4*>(Al + lr*36 + lc + 4*i) = l;
            } else {
                float4 h;
                h.x = f2tff(av.x); h.y = f2tff(av.y); h.z = f2tff(av.z); h.w = f2tff(av.w);
                *reinterpret_cast<float4*>(Ah + lr*36 + lc + 4*i) = h;
            }
            *reinterpret_cast<float4*>(Bs + lr*36 + lc + 4*i) = bv;  // ternary exact
        }
        __syncthreads();
        #pragma unroll
        for (int ks = 0; ks < 4; ks++) {
            int kk = ks*8;
            uint32_t ah[4][4], al[4][4], b[4][2];
            #pragma unroll
            for (int mt = 0; mt < 4; mt++) {
                const float* ph = Ah + (wm + mt*16 + g)*36 + kk + t;
                ah[mt][0] = fu(ph[0]);
                ah[mt][1] = fu(ph[8*36]);
                ah[mt][2] = fu(ph[4]);
                ah[mt][3] = fu(ph[8*36+4]);
                if (ASPLIT) {
                    const float* pl = Al + (wm + mt*16 + g)*36 + kk + t;
                    al[mt][0] = fu(pl[0]);
                    al[mt][1] = fu(pl[8*36]);
                    al[mt][2] = fu(pl[4]);
                    al[mt][3] = fu(pl[8*36+4]);
                }
            }
            #pragma unroll
            for (int nt = 0; nt < 4; nt++) {
                const float* bb = Bs + (wn + nt*8 + g)*36 + kk + t;
                b[nt][0] = fu(bb[0]);
                b[nt][1] = fu(bb[4]);
            }
            #pragma unroll
            for (int mt = 0; mt < 4; mt++)
                #pragma unroll
                for (int nt = 0; nt < 4; nt++) {
                    MMA_TF32(acc[mt][nt], ah[mt], b[nt][0], b[nt][1]);
                    if (ASPLIT) MMA_TF32(acc[mt][nt], al[mt], b[nt][0], b[nt][1]);
                }
        }
        __syncthreads();
    }
    #pragma unroll
    for (int mt = 0; mt < 4; mt++) {
        int r0 = blockIdx.y*128 + wm + mt*16 + g;
        #pragma unroll
        for (int nt = 0; nt < 4; nt++) {
            int c = blockIdx.x*128 + wn + nt*8 + t*2;
            if (SPLIT_OUT) {
                float h0,l0,h1,l1,h2,l2,h3,l3;
                split2(acc[mt][nt][0], h0, l0); split2(acc[mt][nt][1], h1, l1);
                split2(acc[mt][nt][2], h2, l2); split2(acc[mt][nt][3], h3, l3);
                *reinterpret_cast<float2*>(C   + (size_t)r0*N + c)     = make_float2(h0, h1);
                *reinterpret_cast<float2*>(Clo + (size_t)r0*N + c)     = make_float2(l0, l1);
                *reinterpret_cast<float2*>(C   + (size_t)(r0+8)*N + c) = make_float2(h2, h3);
                *reinterpret_cast<float2*>(Clo + (size_t)(r0+8)*N + c) = make_float2(l2, l3);
            } else {
                *reinterpret_cast<float2*>(C + (size_t)r0*N + c) =
                    make_float2(acc[mt][nt][0], acc[mt][nt][1]);
                *reinterpret_cast<float2*>(C + (size_t)(r0+8)*N + c) =
                    make_float2(acc[mt][nt][2], acc[mt][nt][3]);
            }
        }
    }
}

// ---- GQA-merged causal flash attention: 1 CTA = 4 heads x 64 q rows ----
// 8 warps x 32 q-rows. Q/K hi/lo interleaved in smem, V single tf32.
__global__ __launch_bounds__(256) void flash_kernel(
    const float* __restrict__ Qhi, const float* __restrict__ Qlo,
    float* __restrict__ O)
{
    extern __shared__ float smf[];
    float2* Qs = reinterpret_cast<float2*>(smf);          // 256 rows x QPAD float2
    float2* Ks = reinterpret_cast<float2*>(smf + 256*QPAD*2);  // 64 x QPAD float2
    float*  Vs = smf + 256*QPAD*2 + 64*QPAD*2;            // 64 x VPAD floats

    int gcomb = blockIdx.x;          // 0..15 : (kv group, batch)
    int gkv = gcomb >> 1;
    int b   = gcomb & 1;
    int qb  = 31 - blockIdx.y;       // heavy blocks first

    int tid = threadIdx.x;
    int wid = tid >> 5, lane = tid & 31;
    int g = lane >> 2, t = lane & 3;
    int hh = wid >> 1;               // head within kv group (0..3)
    int h  = gkv*4 + hh;
    int wr = (wid & 1) * 32;         // q-row base within this head's 64 rows

    // ---- load Q: 4 heads x 64 rows x 64 cols, {hi,lo} interleaved
    {
        size_t rowbase = (size_t)(b*SEQ + qb*64);
        #pragma unroll
        for (int it = 0; it < 32; it++) {
            int pidx = tid + it*256;       // pair index, 8192 total
            int qrow = pidx >> 5;          // 0..255
            int c2 = pidx & 31;            // pair-of-cols index
            int head = gkv*4 + (qrow >> 6);
            size_t goff = (rowbase + (qrow & 63))*QKV_N + head*HD + c2*2;
            float2 hv = *reinterpret_cast<const float2*>(Qhi + goff);
            float2 lv = *reinterpret_cast<const float2*>(Qlo + goff);
            *reinterpret_cast<float4*>(&Qs[qrow*QPAD + c2*2]) =
                make_float4(hv.x, lv.x, hv.y, lv.y);
        }
    }

    float m_i[4], l_i[4];
    float o_acc[2][8][4];
    #pragma unroll
    for (int i = 0; i < 4; i++) { m_i[i] = -INFINITY; l_i[i] = 0.f; }
    #pragma unroll
    for (int mt = 0; mt < 2; mt++)
        #pragma unroll
        for (int dt = 0; dt < 8; dt++)
            #pragma unroll
            for (int r = 0; r < 4; r++) o_acc[mt][dt][r] = 0.f;

    for (int kb = 0; kb <= qb; kb++) {
        __syncthreads();   // prior PV smem reads done (also covers Q load at kb=0)
        {
            size_t krowbase = (size_t)(b*SEQ + kb*64);
            #pragma unroll
            for (int it = 0; it < 8; it++) {
                int pidx = tid + it*256;
                int kr = pidx >> 5, c2 = pidx & 31;
                size_t goff = (krowbase + kr)*QKV_N + DIMX + gkv*HD + c2*2;
                float2 hv = *reinterpret_cast<const float2*>(Qhi + goff);
                float2 lv = *reinterpret_cast<const float2*>(Qlo + goff);
                *reinterpret_cast<float4*>(&Ks[kr*QPAD + c2*2]) =
                    make_float4(hv.x, lv.x, hv.y, lv.y);
            }
            #pragma unroll
            for (int it = 0; it < 4; it++) {
                int fidx = tid + it*256;
                int vr = fidx >> 4, d4 = fidx & 15;
                size_t goff = (krowbase + vr)*QKV_N + DIMX + KVDIM + gkv*HD + d4*4;
                *reinterpret_cast<float4*>(&Vs[vr*VPAD + d4*4]) =
                    *reinterpret_cast<const float4*>(Qhi + goff);
            }
        }
        __syncthreads();

        // ---- S = Q K^T (3-term split), two m16 tiles per warp
        float s[2][8][4];
        #pragma unroll
        for (int mt = 0; mt < 2; mt++)
            #pragma unroll
            for (int nt = 0; nt < 8; nt++)
                #pragma unroll
                for (int r = 0; r < 4; r++) s[mt][nt][r] = 0.f;

        #pragma unroll
        for (int ks = 0; ks < 8; ks++) {
            int kk = ks*8;
            uint32_t ah[2][4], al[2][4];
            #pragma unroll
            for (int mt = 0; mt < 2; mt++) {
                int row = hh*64 + wr + mt*16 + g;
                float2 q00 = Qs[row*QPAD + kk + t];
                float2 q01 = Qs[row*QPAD + kk + t + 4];
                float2 q10 = Qs[(row+8)*QPAD + kk + t];
                float2 q11 = Qs[(row+8)*QPAD + kk + t + 4];
                ah[mt][0] = fu(q00.x); al[mt][0] = fu(q00.y);
                ah[mt][1] = fu(q10.x); al[mt][1] = fu(q10.y);
                ah[mt][2] = fu(q01.x); al[mt][2] = fu(q01.y);
                ah[mt][3] = fu(q11.x); al[mt][3] = fu(q11.y);
            }
            #pragma unroll
            for (int nt = 0; nt < 8; nt++) {
                float2 k0 = Ks[(nt*8+g)*QPAD + kk + t];
                float2 k1 = Ks[(nt*8+g)*QPAD + kk + t + 4];
                uint32_t bh0 = fu(k0.x), bl0 = fu(k0.y);
                uint32_t bh1 = fu(k1.x), bl1 = fu(k1.y);
                #pragma unroll
                for (int mt = 0; mt < 2; mt++) {
                    MMA_TF32(s[mt][nt], ah[mt], bh0, bh1);
                    MMA_TF32(s[mt][nt], ah[mt], bl0, bl1);
                    MMA_TF32(s[mt][nt], al[mt], bh0, bh1);
                }
            }
        }

        const float smul = 0.125f;   // 1/sqrt(64)
        if (kb == qb) {
            #pragma unroll
            for (int mt = 0; mt < 2; mt++) {
                int qr = wr + mt*16 + g;
                #pragma unroll
                for (int nt = 0; nt < 8; nt++) {
                    int c0 = nt*8 + t*2;
                    s[mt][nt][0] = (c0     <= qr)     ? s[mt][nt][0]*smul : -INFINITY;
                    s[mt][nt][1] = (c0 + 1 <= qr)     ? s[mt][nt][1]*smul : -INFINITY;
                    s[mt][nt][2] = (c0     <= qr + 8) ? s[mt][nt][2]*smul : -INFINITY;
                    s[mt][nt][3] = (c0 + 1 <= qr + 8) ? s[mt][nt][3]*smul : -INFINITY;
                }
            }
        } else {
            #pragma unroll
            for (int mt = 0; mt < 2; mt++)
                #pragma unroll
                for (int nt = 0; nt < 8; nt++)
                    #pragma unroll
                    for (int r = 0; r < 4; r++) s[mt][nt][r] *= smul;
        }

        // ---- online softmax (4 rows/thread: mt x {g, g+8})
        #pragma unroll
        for (int mt = 0; mt < 2; mt++)
            #pragma unroll
            for (int rr = 0; rr < 2; rr++) {
                int si = mt*2 + rr;
                float mx = -INFINITY;
                #pragma unroll
                for (int nt = 0; nt < 8; nt++)
                    mx = fmaxf(mx, fmaxf(s[mt][nt][2*rr], s[mt][nt][2*rr+1]));
                mx = fmaxf(mx, __shfl_xor_sync(0xffffffffu, mx, 1));
                mx = fmaxf(mx, __shfl_xor_sync(0xffffffffu, mx, 2));
                float m_new = fmaxf(m_i[si], mx);
                float alpha = __expf(m_i[si] - m_new);
                float rs = 0.f;
                #pragma unroll
                for (int nt = 0; nt < 8; nt++) {
                    float p0 = __expf(s[mt][nt][2*rr]   - m_new);
                    float p1 = __expf(s[mt][nt][2*rr+1] - m_new);
                    s[mt][nt][2*rr] = p0; s[mt][nt][2*rr+1] = p1;
                    rs += p0 + p1;
                }
                rs += __shfl_xor_sync(0xffffffffu, rs, 1);
                rs += __shfl_xor_sync(0xffffffffu, rs, 2);
                l_i[si] = l_i[si]*alpha + rs;
                m_i[si] = m_new;
                #pragma unroll
                for (int dt = 0; dt < 8; dt++) {
                    o_acc[mt][dt][2*rr]   *= alpha;
                    o_acc[mt][dt][2*rr+1] *= alpha;
                }
            }

        // ---- O += P V  (single tf32; P a-frag assembled via shuffles)
        #pragma unroll
        for (int ks = 0; ks < 8; ks++) {
            int kk = ks*8;
            uint32_t pa[2][4];
            int srcA = (lane & 28) | (t >> 1);
            int srcB = srcA + 2;
            #pragma unroll
            for (int mt = 0; mt < 2; mt++) {
                float x0 = __shfl_sync(0xffffffffu, s[mt][ks][0], srcA);
                float x1 = __shfl_sync(0xffffffffu, s[mt][ks][1], srcA);
                float y0 = __shfl_sync(0xffffffffu, s[mt][ks][0], srcB);
                float y1 = __shfl_sync(0xffffffffu, s[mt][ks][1], srcB);
                float x2 = __shfl_sync(0xffffffffu, s[mt][ks][2], srcA);
                float x3 = __shfl_sync(0xffffffffu, s[mt][ks][3], srcA);
                float y2 = __shfl_sync(0xffffffffu, s[mt][ks][2], srcB);
                float y3 = __shfl_sync(0xffffffffu, s[mt][ks][3], srcB);
                float a0 = (t & 1) ? x1 : x0;
                float a1 = (t & 1) ? x3 : x2;
                float a2 = (t & 1) ? y1 : y0;
                float a3 = (t & 1) ? y3 : y2;
                pa[mt][0] = f2tf(a0); pa[mt][1] = f2tf(a1);
                pa[mt][2] = f2tf(a2); pa[mt][3] = f2tf(a3);
            }
            #pragma unroll
            for (int dt = 0; dt < 8; dt++) {
                uint32_t v0 = fu(Vs[(kk+t)*VPAD + dt*8 + g]);      // already tf32
                uint32_t v1 = fu(Vs[(kk+t+4)*VPAD + dt*8 + g]);
                MMA_TF32(o_acc[0][dt], pa[0], v0, v1);
                MMA_TF32(o_acc[1][dt], pa[1], v0, v1);
            }
        }
    }

    #pragma unroll
    for (int mt = 0; mt < 2; mt++) {
        float inv0 = 1.f / l_i[mt*2];
        float inv1 = 1.f / l_i[mt*2+1];
        float* Og = O + (size_t)(b*SEQ + qb*64 + wr + mt*16 + g)*DIMX + h*HD;
        #pragma unroll
        for (int dt = 0; dt < 8; dt++) {
            *reinterpret_cast<float2*>(Og + dt*8 + t*2) =
                make_float2(o_acc[mt][dt][0]*inv0, o_acc[mt][dt][1]*inv0);
            *reinterpret_cast<float2*>(Og + (size_t)8*DIMX + dt*8 + t*2) =
                make_float2(o_acc[mt][dt][2]*inv1, o_acc[mt][dt][3]*inv1);
        }
    }
}

extern "C" void kernel_launch(void* const* d_in, const int* in_sizes, int n_in,
                              void* d_out, int out_size)
{
    const float* x  = (const float*)d_in[0];
    const float* wq = (const float*)d_in[1];
    const float* wk = (const float*)d_in[2];
    const float* wv = (const float*)d_in[3];
    const float* wo = (const float*)d_in[4];
    float* out = (float*)d_out;

    float *w3, *to, *qh, *ql, *ao;
    cudaGetSymbolAddress((void**)&w3, g_w);
    cudaGetSymbolAddress((void**)&to, g_to);
    cudaGetSymbolAddress((void**)&qh, g_qh);
    cudaGetSymbolAddress((void**)&ql, g_ql);
    cudaGetSymbolAddress((void**)&ao, g_ao);

    abs_partial_kernel<<<1024, 256>>>((const float4*)wq, DIMX*DIMX/4,  0);
    abs_partial_kernel<<<1024, 256>>>((const float4*)wk, KVDIM*DIMX/4, 1);
    abs_partial_kernel<<<1024, 256>>>((const float4*)wv, KVDIM*DIMX/4, 2);
    abs_partial_kernel<<<1024, 256>>>((const float4*)wo, DIMX*DIMX/4,  3);
    finalize_kernel<<<4, 256>>>();

    ternarize_kernel<<<(DIMX*DIMX/4)/256,  256>>>((const float4*)wq, (float4*)w3, DIMX*DIMX/4, 0);
    ternarize_kernel<<<(KVDIM*DIMX/4)/256, 256>>>((const float4*)wk,
        (float4*)(w3 + (size_t)DIMX*DIMX), KVDIM*DIMX/4, 1);
    ternarize_kernel<<<(KVDIM*DIMX/4)/256, 256>>>((const float4*)wv,
        (float4*)(w3 + (size_t)DIMX*DIMX + (size_t)KVDIM*DIMX), KVDIM*DIMX/4, 2);
    ternarize_kernel<<<(DIMX*DIMX/4)/256,  256>>>((const float4*)wo, (float4*)to, DIMX*DIMX/4, 3);

    // QKV projection: split A (exact path), split outputs to hi/lo
    int gsm1 = 3*128*36*4;
    cudaFuncSetAttribute(mma_gemm<true,true>,
                         cudaFuncAttributeMaxDynamicSharedMemorySize, gsm1);
    mma_gemm<true,true><<<dim3(QKV_N/128, M_ROWS/128), 256, gsm1>>>(
        x, w3, qh, ql, QKV_N, DIMX);

    // attention (GQA-merged)
    int fsm = (256*QPAD*2 + 64*QPAD*2 + 64*VPAD) * 4;
    cudaFuncSetAttribute(flash_kernel,
                         cudaFuncAttributeMaxDynamicSharedMemorySize, fsm);
    flash_kernel<<<dim3(16, 32), 256, fsm>>>(qh, ql, ao);

    // output projection: single-tf32 A (within error budget)
    int gsm2 = 2*128*36*4;
    cudaFuncSetAttribute(mma_gemm<false,false>,
                         cudaFuncAttributeMaxDynamicSharedMemorySize, gsm2);
    mma_gemm<false,false><<<dim3(DIMX/128, M_ROWS/128), 256, gsm2>>>(
        ao, to, out, nullptr, DIMX, DIMX);
}